// round 10
// baseline (speedup 1.0000x reference)
#include <cuda_runtime.h>
#include <cuda_bf16.h>
#include <math.h>
#include <stdint.h>

// ---------------- problem constants ----------------
#define NTOK   8192
#define DMODEL 1024
#define DFF    2048
#define NEXP   8
#define TOPK   2

#define TILE     128                  // M per CTA
#define MAX_ROWS 17408                // 16384 + 8*128 padding
#define MAX_TILES (MAX_ROWS / TILE)   // 136

// GEMM tiling
#define BM 128
#define BN 256
#define BK 32
#define NTHREADS 512
#define NSTAGE 4
#define STAGE_FLOATS (BM * BK + BK * BN)          // 4096 + 8192 = 12288
#define SMEM_BYTES   (NSTAGE * STAGE_FLOATS * 4)  // 196608

// ---------------- device scratch ----------------
__device__ int   g_counts[NEXP];
__device__ int   g_cursor[NEXP];
__device__ int   g_rowbase[NEXP];
__device__ int   g_tile_expert[MAX_TILES];
__device__ int   g_total_tiles;
__device__ int   g_done;
__device__ int   g_eids[NTOK * TOPK];
__device__ float g_gates[NTOK * TOPK];
__device__ int   g_slot[NTOK * TOPK];
__device__ float g_Xp[(size_t)MAX_ROWS * DMODEL];   // gathered tokens, tf32-rounded
__device__ float g_H[(size_t)MAX_ROWS * DFF];
__device__ float g_Y[(size_t)MAX_ROWS * DMODEL];

// ---------------- small helpers ----------------
__device__ __forceinline__ uint32_t smem_u32(const void* p) {
    uint32_t a;
    asm("{ .reg .u64 t; cvta.to.shared.u64 t, %1; cvt.u32.u64 %0, t; }"
        : "=r"(a) : "l"(p));
    return a;
}

__device__ __forceinline__ void cp_async16(uint32_t saddr, const float* g) {
    asm volatile("cp.async.cg.shared.global [%0], [%1], 16;"
                 :: "r"(saddr), "l"(g) : "memory");
}
__device__ __forceinline__ void cp_commit() {
    asm volatile("cp.async.commit_group;" ::: "memory");
}
template<int N>
__device__ __forceinline__ void cp_wait() {
    asm volatile("cp.async.wait_group %0;" :: "n"(N) : "memory");
}

__device__ __forceinline__ float rna_tf32(float v) {
    float r;
    asm("cvt.rna.tf32.f32 %0, %1;" : "=f"(r) : "f"(v));
    return r;
}

__device__ __forceinline__ uint32_t rna_tf32_bits(float v) {
    float r;
    asm("cvt.rna.tf32.f32 %0, %1;" : "=f"(r) : "f"(v));
    return __float_as_uint(r);
}

__device__ __forceinline__ void mma_tf32(float& c0, float& c1, float& c2, float& c3,
                                         uint32_t a0, uint32_t a1, uint32_t a2, uint32_t a3,
                                         uint32_t b0, uint32_t b1) {
    asm volatile(
        "mma.sync.aligned.m16n8k8.row.col.f32.tf32.tf32.f32 "
        "{%0,%1,%2,%3}, {%4,%5,%6,%7}, {%8,%9}, {%0,%1,%2,%3};"
        : "+f"(c0), "+f"(c1), "+f"(c2), "+f"(c3)
        : "r"(a0), "r"(a1), "r"(a2), "r"(a3), "r"(b0), "r"(b1));
}

__device__ __forceinline__ float gelu_exact(float v) {
    return 0.5f * v * (1.0f + erff(v * 0.70710678118654752f));
}

// ---------------- pre-pass kernels ----------------
__global__ void init_kernel() {
    int t = threadIdx.x;
    if (t < NEXP) g_counts[t] = 0;
    if (t == NEXP) g_done = 0;
}

// router with fused finalize: the last block to finish performs the
// tile-aligned prefix sum / tile->expert map.
__global__ void router_kernel(const float* __restrict__ x,
                              const float* __restrict__ Wr) {
    __shared__ float sW[NEXP * DMODEL];
    int tid = threadIdx.x;
    for (int i = tid; i < NEXP * DMODEL; i += 256) sW[i] = Wr[i];
    __syncthreads();

    int warp = tid >> 5, lane = tid & 31;
    int tok = blockIdx.x * 8 + warp;

    const float* xr = x + (size_t)tok * DMODEL;
    float acc[NEXP];
#pragma unroll
    for (int e = 0; e < NEXP; e++) acc[e] = 0.f;
    for (int i = lane; i < DMODEL; i += 32) {
        float xv = xr[i];
#pragma unroll
        for (int e = 0; e < NEXP; e++)
            acc[e] = fmaf(xv, sW[e * DMODEL + i], acc[e]);
    }
#pragma unroll
    for (int off = 16; off > 0; off >>= 1)
#pragma unroll
        for (int e = 0; e < NEXP; e++)
            acc[e] += __shfl_xor_sync(0xffffffffu, acc[e], off);
    if (lane == 0) {
        int e0 = 0; float l0 = acc[0];
#pragma unroll
        for (int e = 1; e < NEXP; e++) if (acc[e] > l0) { l0 = acc[e]; e0 = e; }
        int e1 = -1; float l1 = -1e30f;
#pragma unroll
        for (int e = 0; e < NEXP; e++)
            if (e != e0 && acc[e] > l1) { l1 = acc[e]; e1 = e; }
        float g0 = 1.0f / (1.0f + __expf(l1 - l0));
        g_eids[tok * 2 + 0]  = e0;
        g_eids[tok * 2 + 1]  = e1;
        g_gates[tok * 2 + 0] = g0;
        g_gates[tok * 2 + 1] = 1.0f - g0;
        atomicAdd(&g_counts[e0], 1);
        atomicAdd(&g_counts[e1], 1);
    }

    __syncthreads();
    if (tid == 0) {
        __threadfence();
        int ticket = atomicAdd(&g_done, 1);
        if (ticket == (int)gridDim.x - 1) {
            g_done = 0;
            int off = 0, tiles = 0;
            for (int e = 0; e < NEXP; e++) {
                g_rowbase[e] = off;
                g_cursor[e]  = 0;
                int c  = g_counts[e];
                int nt = (c + TILE - 1) / TILE;
                for (int t = 0; t < nt; t++) g_tile_expert[tiles++] = e;
                off += nt * TILE;
            }
            g_total_tiles = tiles;
        }
    }
}

// fused scatter + gather: one block per (token, expert) pair.
__global__ void scatter_gather_kernel(const float* __restrict__ x) {
    __shared__ int srow;
    int i = blockIdx.x;               // pair index
    if (threadIdx.x == 0) {
        int e = g_eids[i];
        int p = atomicAdd(&g_cursor[e], 1);
        int row = g_rowbase[e] + p;
        g_slot[i] = row;
        srow = row;
    }
    __syncthreads();
    int tok = i >> 1;
    const float4* s = (const float4*)(x + (size_t)tok * DMODEL);
    float4* d = (float4*)(g_Xp + (size_t)srow * DMODEL);
    float4 v = s[threadIdx.x];
    v.x = rna_tf32(v.x); v.y = rna_tf32(v.y);
    v.z = rna_tf32(v.z); v.w = rna_tf32(v.w);
    d[threadIdx.x] = v;
}

// ---------------- tf32 mma.sync grouped GEMM (512 threads / 16 warps) ----------------
// A: [rows][KDIM] (m-tile from blockIdx.y), pre-rounded to tf32.
// B: [NEXP][KDIM][NB] raw fp32 weights; fragments rna-rounded in-loop.
// smem A: [m][k] float at m*32 + (k ^ ((m&7)<<2))
// smem B: [k][n] float at k*256 + (n ^ ((k&3)<<3))
// warp grid: 2 (m) x 8 (n); warp tile 64x32.
template<int KDIM, int NB, bool DOGELU>
__global__ __launch_bounds__(NTHREADS, 1)
void mma_gemm(const float* __restrict__ A,
              const float* __restrict__ B,
              const float* __restrict__ bias,
              float* __restrict__ D) {
    int t = blockIdx.y;
    if (t >= g_total_tiles) return;
    int e    = g_tile_expert[t];
    int row0 = t * BM;
    int n0   = blockIdx.x * BN;

    extern __shared__ float smem[];
    uint32_t su = smem_u32(smem);

    int tid  = threadIdx.x;
    int wid  = tid >> 5, lane = tid & 31;
    int wm   = (wid & 1) * 64;          // warp m offset (2 warps)
    int wn   = (wid >> 1) * 32;         // warp n offset (8 warps * 32 = 256)
    int g    = lane >> 2;               // group id 0..7
    int tg   = lane & 3;                // thread-in-group 0..3

    const float* Ag = A + (size_t)row0 * KDIM;
    const float* Bg = B + (size_t)e * KDIM * NB + n0;

    int am  = tid >> 3;                 // A load row 0..63
    int ak4 = (tid & 7) * 4;            // A load k (float index)
    int aks = ak4 ^ ((am & 7) << 2);    // swizzled

    float c[4][4][4];
#pragma unroll
    for (int i = 0; i < 4; i++)
#pragma unroll
        for (int j = 0; j < 4; j++)
#pragma unroll
            for (int q = 0; q < 4; q++) c[i][j][q] = 0.f;

    const int NIT = KDIM / BK;

    auto issue_stage = [&](int it, int st) {
        uint32_t sbase = su + (uint32_t)(st * STAGE_FLOATS) * 4;
        int k0 = it * BK;
        // A: 2 float4 per thread (rows am, am+64)
#pragma unroll
        for (int r = 0; r < 2; r++) {
            int m = am + r * 64;
            cp_async16(sbase + (uint32_t)(m * 32 + aks) * 4,
                       Ag + (size_t)m * KDIM + k0 + ak4);
        }
        // B: 4 float4 per thread
        uint32_t bbase = sbase + (uint32_t)(BM * BK) * 4;
#pragma unroll
        for (int r = 0; r < 4; r++) {
            int idx = tid + r * NTHREADS;
            int k   = idx >> 6;
            int n4  = (idx & 63) * 4;
            int ns  = n4 ^ ((k & 3) << 3);
            cp_async16(bbase + (uint32_t)(k * 256 + ns) * 4,
                       Bg + (size_t)(k0 + k) * NB + n4);
        }
    };

    // prologue: 3 stages in flight
    issue_stage(0, 0); cp_commit();
    issue_stage(1, 1); cp_commit();
    issue_stage(2, 2); cp_commit();

    int swA = g << 2;                   // A k-swizzle per fragment lane
    int swB = tg << 3;                  // B n-swizzle per fragment lane

    for (int it = 0; it < NIT; it++) {
        cp_wait<2>();                   // stage 'it' resident
        __syncthreads();                // stage (it+3)%4 free across all warps
        if (it + 3 < NIT) issue_stage(it + 3, (it + 3) % NSTAGE);
        cp_commit();

        int st = it % NSTAGE;
        const float* sA = smem + st * STAGE_FLOATS;
        const float* sB = sA + BM * BK;

#pragma unroll
        for (int s = 0; s < 4; s++) {
            uint32_t a[4][4];
            uint32_t b[4][2];
            int col0 = (8 * s + tg) ^ swA;
            int col2 = (8 * s + tg + 4) ^ swA;
#pragma unroll
            for (int i = 0; i < 4; i++) {
                int r0 = wm + i * 16 + g;
                a[i][0] = __float_as_uint(sA[r0 * 32 + col0]);
                a[i][1] = __float_as_uint(sA[(r0 + 8) * 32 + col0]);
                a[i][2] = __float_as_uint(sA[r0 * 32 + col2]);
                a[i][3] = __float_as_uint(sA[(r0 + 8) * 32 + col2]);
            }
            int kr0 = (8 * s + tg) * 256;
            int kr1 = (8 * s + tg + 4) * 256;
#pragma unroll
            for (int j = 0; j < 4; j++) {
                int n = (wn + j * 8 + g) ^ swB;
                b[j][0] = rna_tf32_bits(sB[kr0 + n]);
                b[j][1] = rna_tf32_bits(sB[kr1 + n]);
            }
#pragma unroll
            for (int i = 0; i < 4; i++)
#pragma unroll
                for (int j = 0; j < 4; j++)
                    mma_tf32(c[i][j][0], c[i][j][1], c[i][j][2], c[i][j][3],
                             a[i][0], a[i][1], a[i][2], a[i][3],
                             b[j][0], b[j][1]);
        }
    }

    // epilogue
    const float* bp = bias + e * NB + n0 + wn;
    float2 bb[4];
#pragma unroll
    for (int j = 0; j < 4; j++)
        bb[j] = *(const float2*)(bp + j * 8 + 2 * tg);

#pragma unroll
    for (int i = 0; i < 4; i++) {
#pragma unroll
        for (int rr = 0; rr < 2; rr++) {
            int row = row0 + wm + i * 16 + g + rr * 8;
            float* drow = D + (size_t)row * NB + n0 + wn;
#pragma unroll
            for (int j = 0; j < 4; j++) {
                float v0 = c[i][j][rr * 2 + 0] + bb[j].x;
                float v1 = c[i][j][rr * 2 + 1] + bb[j].y;
                if (DOGELU) {
                    v0 = rna_tf32(gelu_exact(v0));
                    v1 = rna_tf32(gelu_exact(v1));
                }
                float2 o = {v0, v1};
                *(float2*)(drow + j * 8 + 2 * tg) = o;
            }
        }
    }
}

// ---------------- combine ----------------
__global__ void combine_kernel(float* __restrict__ out) {
    int i = blockIdx.x * 256 + threadIdx.x;
    const int PER_TOK = DMODEL / 4;
    if (i >= NTOK * PER_TOK) return;
    int tok = i / PER_TOK;
    int d4  = (i - tok * PER_TOK) * 4;
    float g0 = g_gates[tok * 2 + 0];
    float g1 = g_gates[tok * 2 + 1];
    int   r0 = g_slot[tok * 2 + 0];
    int   r1 = g_slot[tok * 2 + 1];
    float4 y0 = *(const float4*)(g_Y + (size_t)r0 * DMODEL + d4);
    float4 y1 = *(const float4*)(g_Y + (size_t)r1 * DMODEL + d4);
    float4 o;
    o.x = g0 * y0.x + g1 * y1.x;
    o.y = g0 * y0.y + g1 * y1.y;
    o.z = g0 * y0.z + g1 * y1.z;
    o.w = g0 * y0.w + g1 * y1.w;
    *(float4*)(out + (size_t)tok * DMODEL + d4) = o;
}

// ---------------- host ----------------
extern "C" void kernel_launch(void* const* d_in, const int* in_sizes, int n_in,
                              void* d_out, int out_size) {
    const float* x  = (const float*)d_in[0];
    const float* Wr = (const float*)d_in[1];
    const float* W1 = (const float*)d_in[2];
    const float* b1 = (const float*)d_in[3];
    const float* W2 = (const float*)d_in[4];
    const float* b2 = (const float*)d_in[5];
    float* out = (float*)d_out;

    void *pXp, *pH, *pY;
    cudaGetSymbolAddress(&pXp, g_Xp);
    cudaGetSymbolAddress(&pH,  g_H);
    cudaGetSymbolAddress(&pY,  g_Y);

    cudaFuncSetAttribute(mma_gemm<DMODEL, DFF, true>,
                         cudaFuncAttributeMaxDynamicSharedMemorySize, SMEM_BYTES);
    cudaFuncSetAttribute(mma_gemm<DFF, DMODEL, false>,
                         cudaFuncAttributeMaxDynamicSharedMemorySize, SMEM_BYTES);

    // launch order: gemm1 is launch index 3 (where ncu lands)
    init_kernel<<<1, 32>>>();                                       // 0
    router_kernel<<<NTOK / 8, 256>>>(x, Wr);                        // 1 (+setup)
    scatter_gather_kernel<<<NTOK * TOPK, 256>>>(x);                 // 2

    // GEMM1: H = gelu(Xp @ W1 + b1), K=1024, N=2048                // 3
    mma_gemm<DMODEL, DFF, true>
        <<<dim3(DFF / BN, MAX_TILES), NTHREADS, SMEM_BYTES>>>(
            (const float*)pXp, W1, b1, (float*)pH);
    // GEMM2: Y = H @ W2 + b2, K=2048, N=1024                       // 4
    mma_gemm<DFF, DMODEL, false>
        <<<dim3(DMODEL / BN, MAX_TILES), NTHREADS, SMEM_BYTES>>>(
            (const float*)pH, W2, b2, (float*)pY);

    combine_kernel<<<(NTOK * DMODEL / 4) / 256, 256>>>(out);        // 5
}

// round 11
// speedup vs baseline: 1.0593x; 1.0593x over previous
#include <cuda_runtime.h>
#include <cuda_bf16.h>
#include <math.h>
#include <stdint.h>

// ---------------- problem constants ----------------
#define NTOK   8192
#define DMODEL 1024
#define DFF    2048
#define NEXP   8
#define TOPK   2

#define TILE     128                  // M per CTA
#define MAX_ROWS 17408                // 16384 + 8*128 padding
#define MAX_TILES (MAX_ROWS / TILE)   // 136

// GEMM tiling (R9 shape: 256 threads, warp tile 64x64)
#define BM 128
#define BN 256
#define BK 32
#define NSTAGE 4
#define STAGE_FLOATS (BM * BK + BK * BN)          // 4096 + 8192 = 12288
#define SMEM_BYTES   (NSTAGE * STAGE_FLOATS * 4)  // 196608

// ---------------- device scratch ----------------
__device__ int   g_counts[NEXP];
__device__ int   g_cursor[NEXP];
__device__ int   g_rowbase[NEXP];
__device__ int   g_tile_expert[MAX_TILES];
__device__ int   g_total_tiles;
__device__ int   g_done;
__device__ int   g_eids[NTOK * TOPK];
__device__ float g_gates[NTOK * TOPK];
__device__ int   g_slot[NTOK * TOPK];
__device__ float g_Xp[(size_t)MAX_ROWS * DMODEL];   // gathered tokens, tf32-rounded
__device__ float g_H[(size_t)MAX_ROWS * DFF];
__device__ float g_Y[(size_t)MAX_ROWS * DMODEL];

// ---------------- small helpers ----------------
__device__ __forceinline__ uint32_t smem_u32(const void* p) {
    uint32_t a;
    asm("{ .reg .u64 t; cvta.to.shared.u64 t, %1; cvt.u32.u64 %0, t; }"
        : "=r"(a) : "l"(p));
    return a;
}

__device__ __forceinline__ void cp_async16(uint32_t saddr, const float* g) {
    asm volatile("cp.async.cg.shared.global [%0], [%1], 16;"
                 :: "r"(saddr), "l"(g) : "memory");
}
__device__ __forceinline__ void cp_commit() {
    asm volatile("cp.async.commit_group;" ::: "memory");
}
template<int N>
__device__ __forceinline__ void cp_wait() {
    asm volatile("cp.async.wait_group %0;" :: "n"(N) : "memory");
}

__device__ __forceinline__ float rna_tf32(float v) {
    float r;
    asm("cvt.rna.tf32.f32 %0, %1;" : "=f"(r) : "f"(v));
    return r;
}

// tf32 MMA hardware reads only bits [31:13] of the b32 operand. Adding
// half-ULP (1<<12) to the raw bits and letting HW truncate implements
// round-to-nearest-away, bit-identical to cvt.rna.tf32.f32 — but as a
// 4-cycle full-rate IADD instead of a ~20-cycle quarter-rate CVT.
__device__ __forceinline__ uint32_t round_bits_tf32(float v) {
    return __float_as_uint(v) + 0x1000u;
}

__device__ __forceinline__ void mma_tf32(float& c0, float& c1, float& c2, float& c3,
                                         uint32_t a0, uint32_t a1, uint32_t a2, uint32_t a3,
                                         uint32_t b0, uint32_t b1) {
    asm volatile(
        "mma.sync.aligned.m16n8k8.row.col.f32.tf32.tf32.f32 "
        "{%0,%1,%2,%3}, {%4,%5,%6,%7}, {%8,%9}, {%0,%1,%2,%3};"
        : "+f"(c0), "+f"(c1), "+f"(c2), "+f"(c3)
        : "r"(a0), "r"(a1), "r"(a2), "r"(a3), "r"(b0), "r"(b1));
}

__device__ __forceinline__ float gelu_exact(float v) {
    return 0.5f * v * (1.0f + erff(v * 0.70710678118654752f));
}

// ---------------- pre-pass kernels ----------------
__global__ void init_kernel() {
    int t = threadIdx.x;
    if (t < NEXP) g_counts[t] = 0;
    if (t == NEXP) g_done = 0;
}

// router with fused finalize: the last block to finish performs the
// tile-aligned prefix sum / tile->expert map.
__global__ void router_kernel(const float* __restrict__ x,
                              const float* __restrict__ Wr) {
    __shared__ float sW[NEXP * DMODEL];
    int tid = threadIdx.x;
    for (int i = tid; i < NEXP * DMODEL; i += 256) sW[i] = Wr[i];
    __syncthreads();

    int warp = tid >> 5, lane = tid & 31;
    int tok = blockIdx.x * 8 + warp;

    const float* xr = x + (size_t)tok * DMODEL;
    float acc[NEXP];
#pragma unroll
    for (int e = 0; e < NEXP; e++) acc[e] = 0.f;
    for (int i = lane; i < DMODEL; i += 32) {
        float xv = xr[i];
#pragma unroll
        for (int e = 0; e < NEXP; e++)
            acc[e] = fmaf(xv, sW[e * DMODEL + i], acc[e]);
    }
#pragma unroll
    for (int off = 16; off > 0; off >>= 1)
#pragma unroll
        for (int e = 0; e < NEXP; e++)
            acc[e] += __shfl_xor_sync(0xffffffffu, acc[e], off);
    if (lane == 0) {
        int e0 = 0; float l0 = acc[0];
#pragma unroll
        for (int e = 1; e < NEXP; e++) if (acc[e] > l0) { l0 = acc[e]; e0 = e; }
        int e1 = -1; float l1 = -1e30f;
#pragma unroll
        for (int e = 0; e < NEXP; e++)
            if (e != e0 && acc[e] > l1) { l1 = acc[e]; e1 = e; }
        float g0 = 1.0f / (1.0f + __expf(l1 - l0));
        g_eids[tok * 2 + 0]  = e0;
        g_eids[tok * 2 + 1]  = e1;
        g_gates[tok * 2 + 0] = g0;
        g_gates[tok * 2 + 1] = 1.0f - g0;
        atomicAdd(&g_counts[e0], 1);
        atomicAdd(&g_counts[e1], 1);
    }

    __syncthreads();
    if (tid == 0) {
        __threadfence();
        int ticket = atomicAdd(&g_done, 1);
        if (ticket == (int)gridDim.x - 1) {
            g_done = 0;
            int off = 0, tiles = 0;
            for (int e = 0; e < NEXP; e++) {
                g_rowbase[e] = off;
                g_cursor[e]  = 0;
                int c  = g_counts[e];
                int nt = (c + TILE - 1) / TILE;
                for (int t = 0; t < nt; t++) g_tile_expert[tiles++] = e;
                off += nt * TILE;
            }
            g_total_tiles = tiles;
        }
    }
}

// fused scatter + gather: one block per (token, expert) pair.
__global__ void scatter_gather_kernel(const float* __restrict__ x) {
    __shared__ int srow;
    int i = blockIdx.x;               // pair index
    if (threadIdx.x == 0) {
        int e = g_eids[i];
        int p = atomicAdd(&g_cursor[e], 1);
        int row = g_rowbase[e] + p;
        g_slot[i] = row;
        srow = row;
    }
    __syncthreads();
    int tok = i >> 1;
    const float4* s = (const float4*)(x + (size_t)tok * DMODEL);
    float4* d = (float4*)(g_Xp + (size_t)srow * DMODEL);
    float4 v = s[threadIdx.x];
    v.x = rna_tf32(v.x); v.y = rna_tf32(v.y);
    v.z = rna_tf32(v.z); v.w = rna_tf32(v.w);
    d[threadIdx.x] = v;
}

// ---------------- tf32 mma.sync grouped GEMM (256 threads, 64x64 warp tile) ----------------
// A: [rows][KDIM] (m-tile from blockIdx.y), pre-rounded to tf32.
// B: [NEXP][KDIM][NB] raw fp32 weights; fragments rounded in-loop via IADD trick.
// smem A: [m][k] float at m*32 + (k ^ ((m&7)<<2))
// smem B: [k][n] float at k*256 + (n ^ ((k&3)<<3))
template<int KDIM, int NB, bool DOGELU>
__global__ __launch_bounds__(256, 1)
void mma_gemm(const float* __restrict__ A,
              const float* __restrict__ B,
              const float* __restrict__ bias,
              float* __restrict__ D) {
    int t = blockIdx.y;
    if (t >= g_total_tiles) return;
    int e    = g_tile_expert[t];
    int row0 = t * BM;
    int n0   = blockIdx.x * BN;

    extern __shared__ float smem[];
    uint32_t su = smem_u32(smem);

    int tid  = threadIdx.x;
    int wid  = tid >> 5, lane = tid & 31;
    int wm   = (wid & 1) * 64;          // warp m offset
    int wn   = (wid >> 1) * 64;         // warp n offset
    int g    = lane >> 2;               // group id 0..7
    int tg   = lane & 3;                // thread-in-group 0..3

    const float* Ag = A + (size_t)row0 * KDIM;
    const float* Bg = B + (size_t)e * KDIM * NB + n0;

    int am  = tid >> 3;                 // A load row
    int ak4 = (tid & 7) * 4;            // A load k (float index)
    int aks = ak4 ^ ((am & 7) << 2);    // swizzled

    float c[4][8][4];
#pragma unroll
    for (int i = 0; i < 4; i++)
#pragma unroll
        for (int j = 0; j < 8; j++)
#pragma unroll
            for (int q = 0; q < 4; q++) c[i][j][q] = 0.f;

    const int NIT = KDIM / BK;

    auto issue_stage = [&](int it, int st) {
        uint32_t sbase = su + (uint32_t)(st * STAGE_FLOATS) * 4;
        int k0 = it * BK;
#pragma unroll
        for (int r = 0; r < 4; r++) {
            int m = am + r * 32;
            cp_async16(sbase + (uint32_t)(m * 32 + aks) * 4,
                       Ag + (size_t)m * KDIM + k0 + ak4);
        }
        uint32_t bbase = sbase + (uint32_t)(BM * BK) * 4;
#pragma unroll
        for (int r = 0; r < 8; r++) {
            int idx = tid + r * 256;
            int k   = idx >> 6;
            int n4  = (idx & 63) * 4;
            int ns  = n4 ^ ((k & 3) << 3);
            cp_async16(bbase + (uint32_t)(k * 256 + ns) * 4,
                       Bg + (size_t)(k0 + k) * NB + n4);
        }
    };

    // prologue: 3 stages in flight
    issue_stage(0, 0); cp_commit();
    issue_stage(1, 1); cp_commit();
    issue_stage(2, 2); cp_commit();

    int swA = g << 2;                   // A k-swizzle per fragment lane
    int swB = tg << 3;                  // B n-swizzle per fragment lane

    for (int it = 0; it < NIT; it++) {
        cp_wait<2>();                   // stage 'it' resident
        __syncthreads();                // stage (it+3)%4 free across all warps
        if (it + 3 < NIT) issue_stage(it + 3, (it + 3) % NSTAGE);
        cp_commit();

        int st = it % NSTAGE;
        const float* sA = smem + st * STAGE_FLOATS;
        const float* sB = sA + BM * BK;

#pragma unroll
        for (int s = 0; s < 4; s++) {
            uint32_t a[4][4];
            uint32_t b[8][2];
            int col0 = (8 * s + tg) ^ swA;
            int col2 = (8 * s + tg + 4) ^ swA;
#pragma unroll
            for (int i = 0; i < 4; i++) {
                int r0 = wm + i * 16 + g;
                a[i][0] = __float_as_uint(sA[r0 * 32 + col0]);
                a[i][1] = __float_as_uint(sA[(r0 + 8) * 32 + col0]);
                a[i][2] = __float_as_uint(sA[r0 * 32 + col2]);
                a[i][3] = __float_as_uint(sA[(r0 + 8) * 32 + col2]);
            }
            int kr0 = (8 * s + tg) * 256;
            int kr1 = (8 * s + tg + 4) * 256;
#pragma unroll
            for (int j = 0; j < 8; j++) {
                int n = (wn + j * 8 + g) ^ swB;
                b[j][0] = round_bits_tf32(sB[kr0 + n]);
                b[j][1] = round_bits_tf32(sB[kr1 + n]);
            }
#pragma unroll
            for (int i = 0; i < 4; i++)
#pragma unroll
                for (int j = 0; j < 8; j++)
                    mma_tf32(c[i][j][0], c[i][j][1], c[i][j][2], c[i][j][3],
                             a[i][0], a[i][1], a[i][2], a[i][3],
                             b[j][0], b[j][1]);
        }
    }

    // epilogue
    const float* bp = bias + e * NB + n0 + wn;
    float2 bb[8];
#pragma unroll
    for (int j = 0; j < 8; j++)
        bb[j] = *(const float2*)(bp + j * 8 + 2 * tg);

#pragma unroll
    for (int i = 0; i < 4; i++) {
#pragma unroll
        for (int rr = 0; rr < 2; rr++) {
            int row = row0 + wm + i * 16 + g + rr * 8;
            float* drow = D + (size_t)row * NB + n0 + wn;
#pragma unroll
            for (int j = 0; j < 8; j++) {
                float v0 = c[i][j][rr * 2 + 0] + bb[j].x;
                float v1 = c[i][j][rr * 2 + 1] + bb[j].y;
                if (DOGELU) {
                    v0 = rna_tf32(gelu_exact(v0));
                    v1 = rna_tf32(gelu_exact(v1));
                }
                float2 o = {v0, v1};
                *(float2*)(drow + j * 8 + 2 * tg) = o;
            }
        }
    }
}

// ---------------- combine ----------------
__global__ void combine_kernel(float* __restrict__ out) {
    int i = blockIdx.x * 256 + threadIdx.x;
    const int PER_TOK = DMODEL / 4;
    if (i >= NTOK * PER_TOK) return;
    int tok = i / PER_TOK;
    int d4  = (i - tok * PER_TOK) * 4;
    float g0 = g_gates[tok * 2 + 0];
    float g1 = g_gates[tok * 2 + 1];
    int   r0 = g_slot[tok * 2 + 0];
    int   r1 = g_slot[tok * 2 + 1];
    float4 y0 = *(const float4*)(g_Y + (size_t)r0 * DMODEL + d4);
    float4 y1 = *(const float4*)(g_Y + (size_t)r1 * DMODEL + d4);
    float4 o;
    o.x = g0 * y0.x + g1 * y1.x;
    o.y = g0 * y0.y + g1 * y1.y;
    o.z = g0 * y0.z + g1 * y1.z;
    o.w = g0 * y0.w + g1 * y1.w;
    *(float4*)(out + (size_t)tok * DMODEL + d4) = o;
}

// ---------------- host ----------------
extern "C" void kernel_launch(void* const* d_in, const int* in_sizes, int n_in,
                              void* d_out, int out_size) {
    const float* x  = (const float*)d_in[0];
    const float* Wr = (const float*)d_in[1];
    const float* W1 = (const float*)d_in[2];
    const float* b1 = (const float*)d_in[3];
    const float* W2 = (const float*)d_in[4];
    const float* b2 = (const float*)d_in[5];
    float* out = (float*)d_out;

    void *pXp, *pH, *pY;
    cudaGetSymbolAddress(&pXp, g_Xp);
    cudaGetSymbolAddress(&pH,  g_H);
    cudaGetSymbolAddress(&pY,  g_Y);

    cudaFuncSetAttribute(mma_gemm<DMODEL, DFF, true>,
                         cudaFuncAttributeMaxDynamicSharedMemorySize, SMEM_BYTES);
    cudaFuncSetAttribute(mma_gemm<DFF, DMODEL, false>,
                         cudaFuncAttributeMaxDynamicSharedMemorySize, SMEM_BYTES);

    // launch order: gemm1 is launch index 3 (where ncu lands)
    init_kernel<<<1, 32>>>();                                       // 0
    router_kernel<<<NTOK / 8, 256>>>(x, Wr);                        // 1 (+setup)
    scatter_gather_kernel<<<NTOK * TOPK, 256>>>(x);                 // 2

    // GEMM1: H = gelu(Xp @ W1 + b1), K=1024, N=2048                // 3
    mma_gemm<DMODEL, DFF, true>
        <<<dim3(DFF / BN, MAX_TILES), 256, SMEM_BYTES>>>(
            (const float*)pXp, W1, b1, (float*)pH);
    // GEMM2: Y = H @ W2 + b2, K=2048, N=1024                       // 4
    mma_gemm<DFF, DMODEL, false>
        <<<dim3(DMODEL / BN, MAX_TILES), 256, SMEM_BYTES>>>(
            (const float*)pH, W2, b2, (float*)pY);

    combine_kernel<<<(NTOK * DMODEL / 4) / 256, 256>>>(out);        // 5
}